// round 13
// baseline (speedup 1.0000x reference)
#include <cuda_runtime.h>
#include <cuda_bf16.h>
#include <math_constants.h>
#include <cstdint>

// Problem constants
#define BATCH 4
#define NSEQ  2048
#define CDIM  1024
#define HEADS 16
#define DH    64
#define MROWS (BATCH*NSEQ)                 // 8192
#define GK    1024
#define KP    3072                         // packed K (3-term split)
#define KQ    192                          // packed head dim (3-term split)
#define QKV_ELEMS (BATCH*HEADS*NSEQ*DH)

// Scratch
__device__ float g_q[QKV_ELEMS];
__device__ float g_k[QKV_ELEMS];
__device__ float g_v[QKV_ELEMS];
__device__ float g_o[MROWS*CDIM];

__device__ __nv_bfloat16 g_xp [MROWS*KP];
__device__ __nv_bfloat16 g_op [MROWS*KP];
__device__ __nv_bfloat16 g_wqp[3*CDIM*KP];
__device__ __nv_bfloat16 g_wpp[CDIM*KP];

__device__ __nv_bfloat16 g_qp  [BATCH*HEADS*NSEQ*KQ];
__device__ __nv_bfloat16 g_kp  [BATCH*HEADS*NSEQ*KQ];
__device__ __nv_bfloat16 g_vthi[BATCH*HEADS*DH*NSEQ];
__device__ __nv_bfloat16 g_vtlo[BATCH*HEADS*DH*NSEQ];

// ---------------------------------------------------------------------------
// helpers
// ---------------------------------------------------------------------------
__device__ __forceinline__ uint32_t smem_u32(const void* p) {
    uint32_t a;
    asm("{ .reg .u64 t; cvta.to.shared.u64 t, %1; cvt.u32.u64 %0, t; }" : "=r"(a) : "l"(p));
    return a;
}
__device__ __forceinline__ void ldsm4(uint32_t* r, uint32_t addr) {
    asm volatile("ldmatrix.sync.aligned.m8n8.x4.shared.b16 {%0,%1,%2,%3}, [%4];"
                 : "=r"(r[0]), "=r"(r[1]), "=r"(r[2]), "=r"(r[3]) : "r"(addr));
}
__device__ __forceinline__ void hmma(float* d, const uint32_t* a, const uint32_t* b) {
    asm volatile(
        "mma.sync.aligned.m16n8k16.row.col.f32.bf16.bf16.f32 "
        "{%0,%1,%2,%3}, {%4,%5,%6,%7}, {%8,%9}, {%0,%1,%2,%3};"
        : "+f"(d[0]), "+f"(d[1]), "+f"(d[2]), "+f"(d[3])
        : "r"(a[0]), "r"(a[1]), "r"(a[2]), "r"(a[3]), "r"(b[0]), "r"(b[1]));
}
__device__ __forceinline__ uint32_t pk2(float e0, float e1) {
    uint32_t r;
    asm("cvt.rn.bf16x2.f32 %0, %1, %2;" : "=r"(r) : "f"(e1), "f"(e0));
    return r;
}
__device__ __forceinline__ float tobf(float v) {
    return __bfloat162float(__float2bfloat16(v));
}
__device__ __forceinline__ void cpasync16(uint32_t dst, const void* src) {
    asm volatile("cp.async.cg.shared.global [%0], [%1], 16;" :: "r"(dst), "l"(src));
}
#define CP_COMMIT()  asm volatile("cp.async.commit_group;" ::: "memory")
#define CP_WAIT0()   asm volatile("cp.async.wait_group 0;" ::: "memory")

// FFMA-only exp (no MUFU): exp(x) for x <= 0, rel err ~2.4e-6.
__device__ __forceinline__ float fast_exp(float x) {
    float y = x * 1.4426950408889634f;
    y = fmaxf(y, -45.0f);
    const float C = 12582912.0f;
    float z  = y + C;
    int   iz = __float_as_int(z);
    float fi = z - C;
    float f  = y - fi;
    float p  = 1.3333558e-3f;
    p = fmaf(p, f, 9.6181291e-3f);
    p = fmaf(p, f, 5.5504109e-2f);
    p = fmaf(p, f, 2.4022651e-1f);
    p = fmaf(p, f, 6.9314718e-1f);
    p = fmaf(p, f, 1.0f);
    int e = ((iz & 0x7FFFFF) - 0x400000) << 23;
    return __int_as_float(__float_as_int(p) + e);
}

// ---------------------------------------------------------------------------
// Pack kernels (vectorized): A=[hi|lo|hi], B=[hi|hi|lo], K'=3072.
// ---------------------------------------------------------------------------
__global__ __launch_bounds__(256)
void pack_a_kernel(const float* __restrict__ src, __nv_bfloat16* __restrict__ dst, int nquads)
{
    const int i = blockIdx.x * blockDim.x + threadIdx.x;
    if (i >= nquads) return;
    const int i4 = i * 4;
    const int m = i4 >> 10, k = i4 & 1023;
    const float4 v = *(const float4*)(src + i4);
    const uint32_t h01 = pk2(v.x, v.y), h23 = pk2(v.z, v.w);
    const uint32_t l01 = pk2(v.x - tobf(v.x), v.y - tobf(v.y));
    const uint32_t l23 = pk2(v.z - tobf(v.z), v.w - tobf(v.w));
    __nv_bfloat16* row = dst + (size_t)m * KP;
    *(uint2*)(row + k)        = make_uint2(h01, h23);
    *(uint2*)(row + k + 1024) = make_uint2(l01, l23);
    *(uint2*)(row + k + 2048) = make_uint2(h01, h23);
}
__global__ __launch_bounds__(256)
void pack_b_kernel(const float* __restrict__ src, __nv_bfloat16* __restrict__ dst, int nquads)
{
    const int i = blockIdx.x * blockDim.x + threadIdx.x;
    if (i >= nquads) return;
    const int i4 = i * 4;
    const int m = i4 >> 10, k = i4 & 1023;
    const float4 v = *(const float4*)(src + i4);
    const uint32_t h01 = pk2(v.x, v.y), h23 = pk2(v.z, v.w);
    const uint32_t l01 = pk2(v.x - tobf(v.x), v.y - tobf(v.y));
    const uint32_t l23 = pk2(v.z - tobf(v.z), v.w - tobf(v.w));
    __nv_bfloat16* row = dst + (size_t)m * KP;
    *(uint2*)(row + k)        = make_uint2(h01, h23);
    *(uint2*)(row + k + 1024) = make_uint2(h01, h23);
    *(uint2*)(row + k + 2048) = make_uint2(l01, l23);
}

// ---------------------------------------------------------------------------
// Dense NT GEMM v4: 128x128 tile, 128 threads, warp tile 64x64 (2x2 warps),
// BK=64, 2-stage cp.async pipeline, 3 CTAs/SM (launch_bounds caps regs).
// Row pitch 144B -> conflict-free ldsm.
// ---------------------------------------------------------------------------
#define GPITCH_B 144
#define GTILE_B (128*GPITCH_B)          // 18432 B per operand tile
#define GSTAGE_B (2*GTILE_B)            // 36864 B per stage
#define GSMEM (2*GSTAGE_B)              // 73728 B

template<int EPI>
__global__ __launch_bounds__(128, 3)
void gemm_mma(const __nv_bfloat16* __restrict__ Ap, const __nv_bfloat16* __restrict__ Bp,
              float* __restrict__ C, int Nglob)
{
    extern __shared__ char smem[];
    const uint32_t sbase = smem_u32(smem);

    const int tid  = threadIdx.x;
    const int wid  = tid >> 5;
    const int lane = tid & 31;
    const int wm   = wid & 1;
    const int wn   = wid >> 1;
    const int m0   = blockIdx.y * 128;
    const int n0   = blockIdx.x * 128;

    const int lrow = tid >> 3;         // 0..15 (x8 row-groups of 16)
    const int lq   = tid & 7;          // quad within 128B row

    const uint32_t a_off = (uint32_t)((wm*64 + (lane & 15)) * GPITCH_B + (lane >> 4) * 16);
    const uint32_t b_off = (uint32_t)((wn*64 + (lane & 7) + ((lane >> 4) << 3)) * GPITCH_B
                                      + ((lane >> 3) & 1) * 16);

    float acc[4][8][4];
    #pragma unroll
    for (int mi = 0; mi < 4; ++mi)
        #pragma unroll
        for (int nf = 0; nf < 8; ++nf)
            #pragma unroll
            for (int j = 0; j < 4; ++j) acc[mi][nf][j] = 0.0f;

    const int T = KP / 64;             // 48

    auto issue = [&](int t) {
        const uint32_t sA = sbase + (t & 1) * GSTAGE_B;
        const uint32_t sB = sA + GTILE_B;
        const int kc = t * 64;
        #pragma unroll
        for (int i = 0; i < 8; ++i) {
            const int row = lrow + i * 16;
            cpasync16(sA + row * GPITCH_B + lq * 16,
                      Ap + (size_t)(m0 + row) * KP + kc + lq * 8);
        }
        #pragma unroll
        for (int i = 0; i < 8; ++i) {
            const int row = lrow + i * 16;
            cpasync16(sB + row * GPITCH_B + lq * 16,
                      Bp + (size_t)(n0 + row) * KP + kc + lq * 8);
        }
    };

    issue(0); CP_COMMIT();

    #pragma unroll 1
    for (int t = 0; t < T; ++t) {
        CP_WAIT0();
        __syncthreads();
        if (t + 1 < T) { issue(t + 1); CP_COMMIT(); }

        const uint32_t sA = sbase + (t & 1) * GSTAGE_B;
        const uint32_t sB = sA + GTILE_B;
        #pragma unroll
        for (int ks = 0; ks < 4; ++ks) {
            uint32_t a[4][4], b[4][4];
            #pragma unroll
            for (int mi = 0; mi < 4; ++mi)
                ldsm4(a[mi], sA + a_off + mi * (16*GPITCH_B) + ks * 32);
            #pragma unroll
            for (int nb = 0; nb < 4; ++nb)
                ldsm4(b[nb], sB + b_off + nb * (16*GPITCH_B) + ks * 32);
            #pragma unroll
            for (int mi = 0; mi < 4; ++mi)
                #pragma unroll
                for (int nb = 0; nb < 4; ++nb) {
                    hmma(acc[mi][nb*2],   a[mi], &b[nb][0]);
                    hmma(acc[mi][nb*2+1], a[mi], &b[nb][2]);
                }
        }
        __syncthreads();   // all warps done reading stage t before its reuse
    }

    const int rbase = m0 + wm * 64 + (lane >> 2);
    const int cbase = n0 + wn * 64 + (lane & 3) * 2;
    #pragma unroll
    for (int mi = 0; mi < 4; ++mi) {
        #pragma unroll
        for (int nf = 0; nf < 8; ++nf) {
            const int r0 = rbase + mi * 16;
            const int c  = cbase + nf * 8;
            const float2 v01 = make_float2(acc[mi][nf][0], acc[mi][nf][1]);
            const float2 v23 = make_float2(acc[mi][nf][2], acc[mi][nf][3]);
            if (EPI == 0) {
                *(float2*)(C + (size_t)r0 * Nglob + c)       = v01;
                *(float2*)(C + (size_t)(r0 + 8) * Nglob + c) = v23;
            } else {
                const int sel = c >> 10;
                const int rem = c & 1023;
                const int h   = rem >> 6;
                const int dcl = rem & 63;
                float* base = (sel == 0) ? g_q : ((sel == 1) ? g_k : g_v);
                {
                    const int m = r0, b = m >> 11, n = m & 2047;
                    *(float2*)(base + (size_t)((b * HEADS + h) * NSEQ + n) * DH + dcl) = v01;
                }
                {
                    const int m = r0 + 8, b = m >> 11, n = m & 2047;
                    *(float2*)(base + (size_t)((b * HEADS + h) * NSEQ + n) * DH + dcl) = v23;
                }
            }
        }
    }
}

// ---------------------------------------------------------------------------
// Fused RMSNorm + RoPE + split-bf16 pack (q scaled by 0.125).
// ---------------------------------------------------------------------------
__global__ __launch_bounds__(256)
void rmsrope_pack_kernel(const float* __restrict__ cosp, const float* __restrict__ sinp,
                         const float* __restrict__ qg, const float* __restrict__ kg)
{
    const int wrow = (blockIdx.x * blockDim.x + threadIdx.x) >> 5;
    const int lane = threadIdx.x & 31;
    const int isq  = (blockIdx.y == 0);
    const float* arr   = isq ? g_q : g_k;
    const float* gamma = isq ? qg  : kg;

    const float* row = arr + (size_t)wrow * DH;
    const int n = wrow & (NSEQ - 1);

    float2 x = *(const float2*)(row + lane * 2);
    float ss = x.x * x.x + x.y * x.y;
    #pragma unroll
    for (int o = 16; o; o >>= 1) ss += __shfl_xor_sync(0xffffffffu, ss, o);
    const float norm = rsqrtf(ss * (1.0f / 64.0f) + 1e-6f);

    const float g0 = gamma[lane * 2], g1 = gamma[lane * 2 + 1];
    const float q0 = x.x * norm * g0;
    const float q1 = x.y * norm * g1;

    const float* cr = cosp + n * DH + lane * 2;
    const float* sr = sinp + n * DH + lane * 2;
    const float scale = isq ? 0.125f : 1.0f;
    const float v0 = (q0 * cr[0] - q1 * sr[0]) * scale;
    const float v1 = (q1 * cr[1] + q0 * sr[1]) * scale;

    const uint32_t HP = pk2(v0, v1);
    const uint32_t LP = pk2(v0 - tobf(v0), v1 - tobf(v1));

    uint32_t* dst = (uint32_t*)((isq ? g_qp : g_kp) + (size_t)wrow * KQ);
    if (isq) { dst[lane] = HP; dst[32 + lane] = LP; dst[64 + lane] = HP; }
    else     { dst[lane] = HP; dst[32 + lane] = HP; dst[64 + lane] = LP; }
}

// ---------------------------------------------------------------------------
// V transpose + split: fp32 g_v (bh,n,d) -> bf16 g_vthi/g_vtlo (bh,d,n).
// ---------------------------------------------------------------------------
__global__ __launch_bounds__(128)
void vtrans_kernel()
{
    __shared__ float s[64 * 68];
    const int tid = threadIdx.x;
    const int n0  = blockIdx.x * 64;
    const int bh  = blockIdx.y;
    const float* src = g_v + ((size_t)bh * NSEQ + n0) * DH;

    #pragma unroll
    for (int it = 0; it < 8; ++it) {
        const int idx = tid + it * 128;
        const int n = idx >> 4, q = (idx & 15) * 4;
        *(float4*)&s[n * 68 + q] = *(const float4*)(src + (size_t)n * DH + q);
    }
    __syncthreads();

    const int d  = tid >> 1;
    const int nh = (tid & 1) * 32;
    uint32_t hibuf[16], lobuf[16];
    #pragma unroll
    for (int j = 0; j < 16; ++j) {
        const float a = s[(nh + 2*j) * 68 + d];
        const float b = s[(nh + 2*j + 1) * 68 + d];
        hibuf[j] = pk2(a, b);
        lobuf[j] = pk2(a - tobf(a), b - tobf(b));
    }
    uint32_t* dh = (uint32_t*)(g_vthi + ((size_t)bh * DH + d) * NSEQ + n0 + nh);
    uint32_t* dl = (uint32_t*)(g_vtlo + ((size_t)bh * DH + d) * NSEQ + n0 + nh);
    #pragma unroll
    for (int j = 0; j < 16; ++j) { dh[j] = hibuf[j]; dl[j] = lobuf[j]; }
}

// ---------------------------------------------------------------------------
// Flash attention v4 (HMMA): 64 q-rows per block, 4 warps, Q fragments held in
// registers (no Q smem) -> smem 88064 B -> 2 CTAs/SM; one CTA's softmax (fma)
// overlaps the other's HMMA. 2-stage cp.async K/V pipeline.
// smem: K 2x25600, V 2x(9216 hi + 9216 lo).
// ---------------------------------------------------------------------------
#define FQ_PITCH 400
#define FV_PITCH 144
#define F_SK   0                          // + st*25600
#define F_SV   51200                      // + st*18432 ; lo at +9216
#define FLASH2_SMEM 88064

__global__ __launch_bounds__(128)
void flash_mma_kernel()
{
    extern __shared__ char sm[];
    const uint32_t sb = smem_u32(sm);
    const int tid  = threadIdx.x;
    const int wid  = tid >> 5;
    const int lane = tid & 31;
    const int q0 = blockIdx.x * 64;
    const int bh = blockIdx.y;

    const __nv_bfloat16* Qg  = g_qp   + ((size_t)bh * NSEQ + q0) * KQ;
    const __nv_bfloat16* Kg  = g_kp   + (size_t)bh * NSEQ * KQ;
    const __nv_bfloat16* Vhg = g_vthi + (size_t)bh * DH * NSEQ;
    const __nv_bfloat16* Vlg = g_vtlo + (size_t)bh * DH * NSEQ;

    // ---- Prologue: stage Q through K-stage-0 smem, ldsm into registers ----
    #pragma unroll
    for (int i = 0; i < 12; ++i) {                       // 64 rows x 24 quads
        const int idx = tid + i * 128;
        const int row = idx / 24, q = idx % 24;
        *(uint4*)(sm + F_SK + row * FQ_PITCH + q * 16) =
            *(const uint4*)(Qg + (size_t)row * KQ + q * 8);
    }
    __syncthreads();
    const uint32_t aq_base = sb + F_SK + (wid * 16 + (lane & 15)) * FQ_PITCH
                             + (lane >> 4) * 16;
    uint32_t qf[12][4];
    #pragma unroll
    for (int ks = 0; ks < 12; ++ks)
        ldsm4(qf[ks], aq_base + ks * 32);
    __syncthreads();                                     // Q reads done before K overwrites

    auto issue_kv = [&](int kt, int st) {
        const uint32_t sk = sb + F_SK + st * 25600;
        const uint32_t sv = sb + F_SV + st * 18432;
        #pragma unroll
        for (int i = 0; i < 12; ++i) {                   // K: 1536 quads
            const int idx = tid + i * 128;
            const int row = idx / 24, q = idx % 24;
            cpasync16(sk + row * FQ_PITCH + q * 16,
                      Kg + (size_t)(kt * 64 + row) * KQ + q * 8);
        }
        #pragma unroll
        for (int i = 0; i < 4; ++i) {                    // Vhi: 512 quads
            const int idx = tid + i * 128;
            const int d = idx >> 3, q = idx & 7;
            cpasync16(sv + d * FV_PITCH + q * 16,
                      Vhg + (size_t)d * NSEQ + kt * 64 + q * 8);
        }
        #pragma unroll
        for (int i = 0; i < 4; ++i) {                    // Vlo: 512 quads
            const int idx = tid + i * 128;
            const int d = idx >> 3, q = idx & 7;
            cpasync16(sv + 9216 + d * FV_PITCH + q * 16,
                      Vlg + (size_t)d * NSEQ + kt * 64 + q * 8);
        }
    };

    issue_kv(0, 0); CP_COMMIT();

    const uint32_t bK_off = ((lane & 7) + ((lane >> 4) << 3)) * FQ_PITCH + ((lane >> 3) & 1) * 16;
    const uint32_t bV_off = ((lane & 7) + ((lane >> 4) << 3)) * FV_PITCH + ((lane >> 3) & 1) * 16;

    float m0 = -CUDART_INF_F, m1 = -CUDART_INF_F, l0 = 0.0f, l1 = 0.0f;
    float oa[8][4];
    #pragma unroll
    for (int i = 0; i < 8; ++i)
        #pragma unroll
        for (int j = 0; j < 4; ++j) oa[i][j] = 0.0f;

    #pragma unroll 1
    for (int kt = 0; kt < NSEQ / 64; ++kt) {
        const int st = kt & 1;
        CP_WAIT0();
        __syncthreads();
        if (kt + 1 < NSEQ / 64) { issue_kv(kt + 1, st ^ 1); CP_COMMIT(); }

        const uint32_t bK_base  = sb + F_SK + st * 25600 + bK_off;
        const uint32_t bVh_base = sb + F_SV + st * 18432 + bV_off;
        const uint32_t bVl_base = bVh_base + 9216;

        // ---- S = Q * K^T over k' = 192 (12 k-steps), Q from registers ----
        float sa[8][4];
        #pragma unroll
        for (int i = 0; i < 8; ++i)
            #pragma unroll
            for (int j = 0; j < 4; ++j) sa[i][j] = 0.0f;

        #pragma unroll
        for (int ks = 0; ks < 12; ++ks) {
            #pragma unroll
            for (int nb = 0; nb < 4; ++nb) {
                uint32_t b[4];
                ldsm4(b, bK_base + nb * (16 * FQ_PITCH) + ks * 32);
                hmma(sa[nb * 2],     qf[ks], &b[0]);
                hmma(sa[nb * 2 + 1], qf[ks], &b[2]);
            }
        }

        // ---- online softmax ----
        float mx0 = sa[0][0], mx1 = sa[0][2];
        #pragma unroll
        for (int nf = 0; nf < 8; ++nf) {
            mx0 = fmaxf(mx0, fmaxf(sa[nf][0], sa[nf][1]));
            mx1 = fmaxf(mx1, fmaxf(sa[nf][2], sa[nf][3]));
        }
        mx0 = fmaxf(mx0, __shfl_xor_sync(0xffffffffu, mx0, 1));
        mx0 = fmaxf(mx0, __shfl_xor_sync(0xffffffffu, mx0, 2));
        mx1 = fmaxf(mx1, __shfl_xor_sync(0xffffffffu, mx1, 1));
        mx1 = fmaxf(mx1, __shfl_xor_sync(0xffffffffu, mx1, 2));

        const float mn0 = fmaxf(m0, mx0);
        const float mn1 = fmaxf(m1, mx1);
        const float al0 = fast_exp(m0 - mn0);
        const float al1 = fast_exp(m1 - mn1);
        m0 = mn0; m1 = mn1;

        float rs0 = 0.0f, rs1 = 0.0f;
        #pragma unroll
        for (int nf = 0; nf < 8; ++nf) {
            sa[nf][0] = fast_exp(sa[nf][0] - mn0);
            sa[nf][1] = fast_exp(sa[nf][1] - mn0);
            sa[nf][2] = fast_exp(sa[nf][2] - mn1);
            sa[nf][3] = fast_exp(sa[nf][3] - mn1);
            rs0 += sa[nf][0] + sa[nf][1];
            rs1 += sa[nf][2] + sa[nf][3];
        }
        rs0 += __shfl_xor_sync(0xffffffffu, rs0, 1);
        rs0 += __shfl_xor_sync(0xffffffffu, rs0, 2);
        rs1 += __shfl_xor_sync(0xffffffffu, rs1, 1);
        rs1 += __shfl_xor_sync(0xffffffffu, rs1, 2);
        l0 = l0 * al0 + rs0;
        l1 = l1 * al1 + rs1;

        #pragma unroll
        for (int nf = 0; nf < 8; ++nf) {
            oa[nf][0] *= al0; oa[nf][1] *= al0;
            oa[nf][2] *= al1; oa[nf][3] *= al1;
        }

        // ---- O += Phi*Vh + Plo*Vh + Phi*Vl ----
        #pragma unroll
        for (int ks = 0; ks < 4; ++ks) {
            const int f0 = 2 * ks, f1 = 2 * ks + 1;
            uint32_t ah[4], al_[4];
            {
                const float p00 = sa[f0][0], p01 = sa[f0][1];
                const float p02 = sa[f0][2], p03 = sa[f0][3];
                const float p10 = sa[f1][0], p11 = sa[f1][1];
                const float p12 = sa[f1][2], p13 = sa[f1][3];
                ah[0] = pk2(p00, p01);
                ah[1] = pk2(p02, p03);
                ah[2] = pk2(p10, p11);
                ah[3] = pk2(p12, p13);
                al_[0] = pk2(p00 - tobf(p00), p01 - tobf(p01));
                al_[1] = pk2(p02 - tobf(p02), p03 - tobf(p03));
                al_[2] = pk2(p10 - tobf(p10), p11 - tobf(p11));
                al_[3] = pk2(p12 - tobf(p12), p13 - tobf(p13));
            }
            #pragma unroll
            for (int nb = 0; nb < 4; ++nb) {
                uint32_t bh_[4], bl_[4];
                ldsm4(bh_, bVh_base + nb * (16 * FV_PITCH) + ks * 32);
                hmma(oa[nb * 2],     ah,  &bh_[0]);
                hmma(oa[nb * 2 + 1], ah,  &bh_[2]);
                hmma(oa[nb * 2],     al_, &bh_[0]);
                hmma(oa[nb * 2 + 1], al_, &bh_[2]);
                ldsm4(bl_, bVl_base + nb * (16 * FV_PITCH) + ks * 32);
                hmma(oa[nb * 2],     ah,  &bl_[0]);
                hmma(oa[nb * 2 + 1], ah,  &bl_[2]);
            }
        }
    }

    // ---- writeout ----
    const int b = bh >> 4;
    const int h = bh & 15;
    const int r0 = q0 + wid * 16 + (lane >> 2);
    const float i0 = 1.0f / l0;
    const float i1 = 1.0f / l1;
    #pragma unroll
    for (int idx = 0; idx < 8; ++idx) {
        const int d = idx * 8 + (lane & 3) * 2;
        float* p0 = g_o + (size_t)(b * NSEQ + r0) * CDIM + h * DH + d;
        float* p1 = g_o + (size_t)(b * NSEQ + r0 + 8) * CDIM + h * DH + d;
        *(float2*)p0 = make_float2(oa[idx][0] * i0, oa[idx][1] * i0);
        *(float2*)p1 = make_float2(oa[idx][2] * i1, oa[idx][3] * i1);
    }
}

// ---------------------------------------------------------------------------
// Launch
// ---------------------------------------------------------------------------
extern "C" void kernel_launch(void* const* d_in, const int* in_sizes, int n_in,
                              void* d_out, int out_size)
{
    const float* x      = (const float*)d_in[0];
    const float* cosp   = (const float*)d_in[1];
    const float* sinp   = (const float*)d_in[2];
    const float* w_qkv  = (const float*)d_in[3];
    const float* w_proj = (const float*)d_in[4];
    const float* qg     = (const float*)d_in[5];
    const float* kg     = (const float*)d_in[6];
    float* out          = (float*)d_out;
    (void)in_sizes; (void)n_in; (void)out_size;

    cudaFuncSetAttribute(gemm_mma<0>, cudaFuncAttributeMaxDynamicSharedMemorySize, GSMEM);
    cudaFuncSetAttribute(gemm_mma<1>, cudaFuncAttributeMaxDynamicSharedMemorySize, GSMEM);
    cudaFuncSetAttribute(flash_mma_kernel, cudaFuncAttributeMaxDynamicSharedMemorySize, FLASH2_SMEM);

    void *p_go, *p_xp, *p_op, *p_wqp, *p_wpp;
    cudaGetSymbolAddress(&p_go,  g_o);
    cudaGetSymbolAddress(&p_xp,  g_xp);
    cudaGetSymbolAddress(&p_op,  g_op);
    cudaGetSymbolAddress(&p_wqp, g_wqp);
    cudaGetSymbolAddress(&p_wpp, g_wpp);

    // 0) Pack dense-GEMM operands (vectorized: 4 elems/thread)
    pack_a_kernel<<<(MROWS*GK/4  + 255)/256, 256>>>(x,      (__nv_bfloat16*)p_xp,  MROWS*GK/4);
    pack_b_kernel<<<(3*CDIM*GK/4 + 255)/256, 256>>>(w_qkv,  (__nv_bfloat16*)p_wqp, 3*CDIM*GK/4);
    pack_b_kernel<<<(CDIM*GK/4   + 255)/256, 256>>>(w_proj, (__nv_bfloat16*)p_wpp, CDIM*GK/4);

    // 1) QKV GEMM -> fp32 g_q/g_k/g_v (B,H,N,D)
    gemm_mma<1><<<dim3(3*CDIM/128, MROWS/128), 128, GSMEM>>>(
        (const __nv_bfloat16*)p_xp, (const __nv_bfloat16*)p_wqp, nullptr, 3*CDIM);

    // 2) RMSNorm + RoPE + pack;  V transpose + split
    rmsrope_pack_kernel<<<dim3((2*BATCH*HEADS*NSEQ)/16, 2), 256>>>(cosp, sinp, qg, kg);
    vtrans_kernel<<<dim3(NSEQ/64, BATCH*HEADS), 128>>>();

    // 3) Flash attention (HMMA, 64-q blocks, Q in regs, 2 CTAs/SM) -> g_o (B,N,C)
    flash_mma_kernel<<<dim3(NSEQ/64, BATCH*HEADS), 128, FLASH2_SMEM>>>();

    // 4) Pack attention output, projection GEMM
    pack_a_kernel<<<(MROWS*GK/4 + 255)/256, 256>>>((const float*)p_go, (__nv_bfloat16*)p_op, MROWS*GK/4);
    gemm_mma<0><<<dim3(CDIM/128, MROWS/128), 128, GSMEM>>>(
        (const __nv_bfloat16*)p_op, (const __nv_bfloat16*)p_wpp, out, CDIM);
}

// round 15
// speedup vs baseline: 1.1421x; 1.1421x over previous
#include <cuda_runtime.h>
#include <cuda_bf16.h>
#include <math_constants.h>
#include <cstdint>

// Problem constants
#define BATCH 4
#define NSEQ  2048
#define CDIM  1024
#define HEADS 16
#define DH    64
#define MROWS (BATCH*NSEQ)                 // 8192
#define GK    1024
#define KP    3072                         // packed K (3-term split)
#define KQ    192                          // packed head dim (3-term split)
#define QKV_ELEMS (BATCH*HEADS*NSEQ*DH)

// Scratch
__device__ float g_q[QKV_ELEMS];
__device__ float g_k[QKV_ELEMS];
__device__ float g_v[QKV_ELEMS];
__device__ float g_o[MROWS*CDIM];

__device__ __nv_bfloat16 g_xp [MROWS*KP];
__device__ __nv_bfloat16 g_op [MROWS*KP];
__device__ __nv_bfloat16 g_wqp[3*CDIM*KP];
__device__ __nv_bfloat16 g_wpp[CDIM*KP];

__device__ __nv_bfloat16 g_qp  [BATCH*HEADS*NSEQ*KQ];
__device__ __nv_bfloat16 g_kp  [BATCH*HEADS*NSEQ*KQ];
__device__ __nv_bfloat16 g_vthi[BATCH*HEADS*DH*NSEQ];
__device__ __nv_bfloat16 g_vtlo[BATCH*HEADS*DH*NSEQ];

// ---------------------------------------------------------------------------
// helpers
// ---------------------------------------------------------------------------
__device__ __forceinline__ uint32_t smem_u32(const void* p) {
    uint32_t a;
    asm("{ .reg .u64 t; cvta.to.shared.u64 t, %1; cvt.u32.u64 %0, t; }" : "=r"(a) : "l"(p));
    return a;
}
__device__ __forceinline__ void ldsm4(uint32_t* r, uint32_t addr) {
    asm volatile("ldmatrix.sync.aligned.m8n8.x4.shared.b16 {%0,%1,%2,%3}, [%4];"
                 : "=r"(r[0]), "=r"(r[1]), "=r"(r[2]), "=r"(r[3]) : "r"(addr));
}
__device__ __forceinline__ void hmma(float* d, const uint32_t* a, const uint32_t* b) {
    asm volatile(
        "mma.sync.aligned.m16n8k16.row.col.f32.bf16.bf16.f32 "
        "{%0,%1,%2,%3}, {%4,%5,%6,%7}, {%8,%9}, {%0,%1,%2,%3};"
        : "+f"(d[0]), "+f"(d[1]), "+f"(d[2]), "+f"(d[3])
        : "r"(a[0]), "r"(a[1]), "r"(a[2]), "r"(a[3]), "r"(b[0]), "r"(b[1]));
}
__device__ __forceinline__ uint32_t pk2(float e0, float e1) {
    uint32_t r;
    asm("cvt.rn.bf16x2.f32 %0, %1, %2;" : "=r"(r) : "f"(e1), "f"(e0));
    return r;
}
__device__ __forceinline__ float tobf(float v) {
    return __bfloat162float(__float2bfloat16(v));
}
__device__ __forceinline__ void cpasync16(uint32_t dst, const void* src) {
    asm volatile("cp.async.cg.shared.global [%0], [%1], 16;" :: "r"(dst), "l"(src));
}
#define CP_COMMIT()  asm volatile("cp.async.commit_group;" ::: "memory")
#define CP_WAIT0()   asm volatile("cp.async.wait_group 0;" ::: "memory")

// FFMA-only exp (no MUFU): exp(x) for x <= 0, rel err ~2.4e-6.
__device__ __forceinline__ float fast_exp(float x) {
    float y = x * 1.4426950408889634f;
    y = fmaxf(y, -45.0f);
    const float C = 12582912.0f;
    float z  = y + C;
    int   iz = __float_as_int(z);
    float fi = z - C;
    float f  = y - fi;
    float p  = 1.3333558e-3f;
    p = fmaf(p, f, 9.6181291e-3f);
    p = fmaf(p, f, 5.5504109e-2f);
    p = fmaf(p, f, 2.4022651e-1f);
    p = fmaf(p, f, 6.9314718e-1f);
    p = fmaf(p, f, 1.0f);
    int e = ((iz & 0x7FFFFF) - 0x400000) << 23;
    return __int_as_float(__float_as_int(p) + e);
}

// ---------------------------------------------------------------------------
// Pack kernels (vectorized): A=[hi|lo|hi], B=[hi|hi|lo], K'=3072.
// ---------------------------------------------------------------------------
__global__ __launch_bounds__(256)
void pack_a_kernel(const float* __restrict__ src, __nv_bfloat16* __restrict__ dst, int nquads)
{
    const int i = blockIdx.x * blockDim.x + threadIdx.x;
    if (i >= nquads) return;
    const int i4 = i * 4;
    const int m = i4 >> 10, k = i4 & 1023;
    const float4 v = *(const float4*)(src + i4);
    const uint32_t h01 = pk2(v.x, v.y), h23 = pk2(v.z, v.w);
    const uint32_t l01 = pk2(v.x - tobf(v.x), v.y - tobf(v.y));
    const uint32_t l23 = pk2(v.z - tobf(v.z), v.w - tobf(v.w));
    __nv_bfloat16* row = dst + (size_t)m * KP;
    *(uint2*)(row + k)        = make_uint2(h01, h23);
    *(uint2*)(row + k + 1024) = make_uint2(l01, l23);
    *(uint2*)(row + k + 2048) = make_uint2(h01, h23);
}
__global__ __launch_bounds__(256)
void pack_b_kernel(const float* __restrict__ src, __nv_bfloat16* __restrict__ dst, int nquads)
{
    const int i = blockIdx.x * blockDim.x + threadIdx.x;
    if (i >= nquads) return;
    const int i4 = i * 4;
    const int m = i4 >> 10, k = i4 & 1023;
    const float4 v = *(const float4*)(src + i4);
    const uint32_t h01 = pk2(v.x, v.y), h23 = pk2(v.z, v.w);
    const uint32_t l01 = pk2(v.x - tobf(v.x), v.y - tobf(v.y));
    const uint32_t l23 = pk2(v.z - tobf(v.z), v.w - tobf(v.w));
    __nv_bfloat16* row = dst + (size_t)m * KP;
    *(uint2*)(row + k)        = make_uint2(h01, h23);
    *(uint2*)(row + k + 1024) = make_uint2(h01, h23);
    *(uint2*)(row + k + 2048) = make_uint2(l01, l23);
}

// ---------------------------------------------------------------------------
// Dense NT GEMM v4 (measured best): 128x128 tile, 128 threads, warp 64x64,
// BK=64, 2-stage cp.async pipeline, 3 CTAs/SM. Row pitch 144B.
// ---------------------------------------------------------------------------
#define GPITCH_B 144
#define GTILE_B (128*GPITCH_B)          // 18432 B per operand tile
#define GSTAGE_B (2*GTILE_B)            // 36864 B per stage
#define GSMEM (2*GSTAGE_B)              // 73728 B

template<int EPI>
__global__ __launch_bounds__(128, 3)
void gemm_mma(const __nv_bfloat16* __restrict__ Ap, const __nv_bfloat16* __restrict__ Bp,
              float* __restrict__ C, int Nglob)
{
    extern __shared__ char smem[];
    const uint32_t sbase = smem_u32(smem);

    const int tid  = threadIdx.x;
    const int wid  = tid >> 5;
    const int lane = tid & 31;
    const int wm   = wid & 1;
    const int wn   = wid >> 1;
    const int m0   = blockIdx.y * 128;
    const int n0   = blockIdx.x * 128;

    const int lrow = tid >> 3;         // 0..15 (x8 row-groups of 16)
    const int lq   = tid & 7;          // quad within 128B row

    const uint32_t a_off = (uint32_t)((wm*64 + (lane & 15)) * GPITCH_B + (lane >> 4) * 16);
    const uint32_t b_off = (uint32_t)((wn*64 + (lane & 7) + ((lane >> 4) << 3)) * GPITCH_B
                                      + ((lane >> 3) & 1) * 16);

    float acc[4][8][4];
    #pragma unroll
    for (int mi = 0; mi < 4; ++mi)
        #pragma unroll
        for (int nf = 0; nf < 8; ++nf)
            #pragma unroll
            for (int j = 0; j < 4; ++j) acc[mi][nf][j] = 0.0f;

    const int T = KP / 64;             // 48

    auto issue = [&](int t) {
        const uint32_t sA = sbase + (t & 1) * GSTAGE_B;
        const uint32_t sB = sA + GTILE_B;
        const int kc = t * 64;
        #pragma unroll
        for (int i = 0; i < 8; ++i) {
            const int row = lrow + i * 16;
            cpasync16(sA + row * GPITCH_B + lq * 16,
                      Ap + (size_t)(m0 + row) * KP + kc + lq * 8);
        }
        #pragma unroll
        for (int i = 0; i < 8; ++i) {
            const int row = lrow + i * 16;
            cpasync16(sB + row * GPITCH_B + lq * 16,
                      Bp + (size_t)(n0 + row) * KP + kc + lq * 8);
        }
    };

    issue(0); CP_COMMIT();

    #pragma unroll 1
    for (int t = 0; t < T; ++t) {
        CP_WAIT0();
        __syncthreads();
        if (t + 1 < T) { issue(t + 1); CP_COMMIT(); }

        const uint32_t sA = sbase + (t & 1) * GSTAGE_B;
        const uint32_t sB = sA + GTILE_B;
        #pragma unroll
        for (int ks = 0; ks < 4; ++ks) {
            uint32_t a[4][4], b[4][4];
            #pragma unroll
            for (int mi = 0; mi < 4; ++mi)
                ldsm4(a[mi], sA + a_off + mi * (16*GPITCH_B) + ks * 32);
            #pragma unroll
            for (int nb = 0; nb < 4; ++nb)
                ldsm4(b[nb], sB + b_off + nb * (16*GPITCH_B) + ks * 32);
            #pragma unroll
            for (int mi = 0; mi < 4; ++mi)
                #pragma unroll
                for (int nb = 0; nb < 4; ++nb) {
                    hmma(acc[mi][nb*2],   a[mi], &b[nb][0]);
                    hmma(acc[mi][nb*2+1], a[mi], &b[nb][2]);
                }
        }
        __syncthreads();   // all warps done reading stage t before its reuse
    }

    const int rbase = m0 + wm * 64 + (lane >> 2);
    const int cbase = n0 + wn * 64 + (lane & 3) * 2;
    #pragma unroll
    for (int mi = 0; mi < 4; ++mi) {
        #pragma unroll
        for (int nf = 0; nf < 8; ++nf) {
            const int r0 = rbase + mi * 16;
            const int c  = cbase + nf * 8;
            const float2 v01 = make_float2(acc[mi][nf][0], acc[mi][nf][1]);
            const float2 v23 = make_float2(acc[mi][nf][2], acc[mi][nf][3]);
            if (EPI == 0) {
                *(float2*)(C + (size_t)r0 * Nglob + c)       = v01;
                *(float2*)(C + (size_t)(r0 + 8) * Nglob + c) = v23;
            } else {
                const int sel = c >> 10;
                const int rem = c & 1023;
                const int h   = rem >> 6;
                const int dcl = rem & 63;
                float* base = (sel == 0) ? g_q : ((sel == 1) ? g_k : g_v);
                {
                    const int m = r0, b = m >> 11, n = m & 2047;
                    *(float2*)(base + (size_t)((b * HEADS + h) * NSEQ + n) * DH + dcl) = v01;
                }
                {
                    const int m = r0 + 8, b = m >> 11, n = m & 2047;
                    *(float2*)(base + (size_t)((b * HEADS + h) * NSEQ + n) * DH + dcl) = v23;
                }
            }
        }
    }
}

// ---------------------------------------------------------------------------
// Fused RMSNorm + RoPE + split-bf16 pack (q scaled by 0.125).
// ---------------------------------------------------------------------------
__global__ __launch_bounds__(256)
void rmsrope_pack_kernel(const float* __restrict__ cosp, const float* __restrict__ sinp,
                         const float* __restrict__ qg, const float* __restrict__ kg)
{
    const int wrow = (blockIdx.x * blockDim.x + threadIdx.x) >> 5;
    const int lane = threadIdx.x & 31;
    const int isq  = (blockIdx.y == 0);
    const float* arr   = isq ? g_q : g_k;
    const float* gamma = isq ? qg  : kg;

    const float* row = arr + (size_t)wrow * DH;
    const int n = wrow & (NSEQ - 1);

    float2 x = *(const float2*)(row + lane * 2);
    float ss = x.x * x.x + x.y * x.y;
    #pragma unroll
    for (int o = 16; o; o >>= 1) ss += __shfl_xor_sync(0xffffffffu, ss, o);
    const float norm = rsqrtf(ss * (1.0f / 64.0f) + 1e-6f);

    const float g0 = gamma[lane * 2], g1 = gamma[lane * 2 + 1];
    const float q0 = x.x * norm * g0;
    const float q1 = x.y * norm * g1;

    const float* cr = cosp + n * DH + lane * 2;
    const float* sr = sinp + n * DH + lane * 2;
    const float scale = isq ? 0.125f : 1.0f;
    const float v0 = (q0 * cr[0] - q1 * sr[0]) * scale;
    const float v1 = (q1 * cr[1] + q0 * sr[1]) * scale;

    const uint32_t HP = pk2(v0, v1);
    const uint32_t LP = pk2(v0 - tobf(v0), v1 - tobf(v1));

    uint32_t* dst = (uint32_t*)((isq ? g_qp : g_kp) + (size_t)wrow * KQ);
    if (isq) { dst[lane] = HP; dst[32 + lane] = LP; dst[64 + lane] = HP; }
    else     { dst[lane] = HP; dst[32 + lane] = HP; dst[64 + lane] = LP; }
}

// ---------------------------------------------------------------------------
// V transpose + split: fp32 g_v (bh,n,d) -> bf16 g_vthi/g_vtlo (bh,d,n).
// ---------------------------------------------------------------------------
__global__ __launch_bounds__(128)
void vtrans_kernel()
{
    __shared__ float s[64 * 68];
    const int tid = threadIdx.x;
    const int n0  = blockIdx.x * 64;
    const int bh  = blockIdx.y;
    const float* src = g_v + ((size_t)bh * NSEQ + n0) * DH;

    #pragma unroll
    for (int it = 0; it < 8; ++it) {
        const int idx = tid + it * 128;
        const int n = idx >> 4, q = (idx & 15) * 4;
        *(float4*)&s[n * 68 + q] = *(const float4*)(src + (size_t)n * DH + q);
    }
    __syncthreads();

    const int d  = tid >> 1;
    const int nh = (tid & 1) * 32;
    uint32_t hibuf[16], lobuf[16];
    #pragma unroll
    for (int j = 0; j < 16; ++j) {
        const float a = s[(nh + 2*j) * 68 + d];
        const float b = s[(nh + 2*j + 1) * 68 + d];
        hibuf[j] = pk2(a, b);
        lobuf[j] = pk2(a - tobf(a), b - tobf(b));
    }
    uint32_t* dh = (uint32_t*)(g_vthi + ((size_t)bh * DH + d) * NSEQ + n0 + nh);
    uint32_t* dl = (uint32_t*)(g_vtlo + ((size_t)bh * DH + d) * NSEQ + n0 + nh);
    #pragma unroll
    for (int j = 0; j < 16; ++j) { dh[j] = hibuf[j]; dl[j] = lobuf[j]; }
}

// ---------------------------------------------------------------------------
// Flash attention v3 (measured best): 256 q-rows per block, 8 warps; warp owns
// 32 q rows (two m16 tiles sharing K/V fragments). 2-stage cp.async pipeline.
// smem: Q 256x400 = 102400, K 2x25600, V 2x(9216 hi + 9216 lo) = 190464 B.
// ---------------------------------------------------------------------------
#define FQ_PITCH 400
#define FV_PITCH 144
#define F_SQ   0
#define F_SK   102400                     // + st*25600
#define F_SV   153600                     // + st*18432 ; lo at +9216
#define FLASH2_SMEM 190464

__global__ __launch_bounds__(256)
void flash_mma_kernel()
{
    extern __shared__ char sm[];
    const uint32_t sb = smem_u32(sm);
    const int tid  = threadIdx.x;
    const int wid  = tid >> 5;
    const int lane = tid & 31;
    const int q0 = blockIdx.x * 256;
    const int bh = blockIdx.y;

    const __nv_bfloat16* Qg  = g_qp   + ((size_t)bh * NSEQ + q0) * KQ;
    const __nv_bfloat16* Kg  = g_kp   + (size_t)bh * NSEQ * KQ;
    const __nv_bfloat16* Vhg = g_vthi + (size_t)bh * DH * NSEQ;
    const __nv_bfloat16* Vlg = g_vtlo + (size_t)bh * DH * NSEQ;

    auto issue_kv = [&](int kt, int st) {
        const uint32_t sk = sb + F_SK + st * 25600;
        const uint32_t sv = sb + F_SV + st * 18432;
        #pragma unroll
        for (int i = 0; i < 6; ++i) {                    // K: 1536 quads
            const int idx = tid + i * 256;
            const int row = idx / 24, q = idx % 24;
            cpasync16(sk + row * FQ_PITCH + q * 16,
                      Kg + (size_t)(kt * 64 + row) * KQ + q * 8);
        }
        #pragma unroll
        for (int i = 0; i < 2; ++i) {                    // Vhi: 512 quads
            const int idx = tid + i * 256;
            const int d = idx >> 3, q = idx & 7;
            cpasync16(sv + d * FV_PITCH + q * 16,
                      Vhg + (size_t)d * NSEQ + kt * 64 + q * 8);
        }
        #pragma unroll
        for (int i = 0; i < 2; ++i) {                    // Vlo: 512 quads
            const int idx = tid + i * 256;
            const int d = idx >> 3, q = idx & 7;
            cpasync16(sv + 9216 + d * FV_PITCH + q * 16,
                      Vlg + (size_t)d * NSEQ + kt * 64 + q * 8);
        }
    };

    issue_kv(0, 0); CP_COMMIT();

    // Load Q tile: 256 rows x 24 quads = 6144 quads, 24 per thread
    #pragma unroll
    for (int i = 0; i < 24; ++i) {
        const int idx = tid + i * 256;
        const int row = idx / 24, q = idx % 24;
        *(uint4*)(sm + F_SQ + row * FQ_PITCH + q * 16) =
            *(const uint4*)(Qg + (size_t)row * KQ + q * 8);
    }

    // ldmatrix bases
    uint32_t a_base[2];
    #pragma unroll
    for (int mt = 0; mt < 2; ++mt)
        a_base[mt] = sb + F_SQ + (wid * 32 + mt * 16 + (lane & 15)) * FQ_PITCH
                     + (lane >> 4) * 16;
    const uint32_t bK_off = ((lane & 7) + ((lane >> 4) << 3)) * FQ_PITCH + ((lane >> 3) & 1) * 16;
    const uint32_t bV_off = ((lane & 7) + ((lane >> 4) << 3)) * FV_PITCH + ((lane >> 3) & 1) * 16;

    float m_[2][2], l_[2][2];
    float oa[2][8][4];
    #pragma unroll
    for (int mt = 0; mt < 2; ++mt) {
        m_[mt][0] = -CUDART_INF_F; m_[mt][1] = -CUDART_INF_F;
        l_[mt][0] = 0.0f; l_[mt][1] = 0.0f;
        #pragma unroll
        for (int i = 0; i < 8; ++i)
            #pragma unroll
            for (int j = 0; j < 4; ++j) oa[mt][i][j] = 0.0f;
    }

    #pragma unroll 1
    for (int kt = 0; kt < NSEQ / 64; ++kt) {
        const int st = kt & 1;
        CP_WAIT0();
        __syncthreads();
        if (kt + 1 < NSEQ / 64) { issue_kv(kt + 1, st ^ 1); CP_COMMIT(); }

        const uint32_t bK_base  = sb + F_SK + st * 25600 + bK_off;
        const uint32_t bVh_base = sb + F_SV + st * 18432 + bV_off;
        const uint32_t bVl_base = bVh_base + 9216;

        // ---- S = Q * K^T over k' = 192 (12 k-steps); K frags shared by both mt ----
        float sa[2][8][4];
        #pragma unroll
        for (int mt = 0; mt < 2; ++mt)
            #pragma unroll
            for (int i = 0; i < 8; ++i)
                #pragma unroll
                for (int j = 0; j < 4; ++j) sa[mt][i][j] = 0.0f;

        #pragma unroll
        for (int ks = 0; ks < 12; ++ks) {
            uint32_t b[4][4];
            #pragma unroll
            for (int nb = 0; nb < 4; ++nb)
                ldsm4(b[nb], bK_base + nb * (16 * FQ_PITCH) + ks * 32);
            #pragma unroll
            for (int mt = 0; mt < 2; ++mt) {
                uint32_t a[4];
                ldsm4(a, a_base[mt] + ks * 32);
                #pragma unroll
                for (int nb = 0; nb < 4; ++nb) {
                    hmma(sa[mt][nb * 2],     a, &b[nb][0]);
                    hmma(sa[mt][nb * 2 + 1], a, &b[nb][2]);
                }
            }
        }

        // ---- online softmax per mt ----
        #pragma unroll
        for (int mt = 0; mt < 2; ++mt) {
            float mx0 = sa[mt][0][0], mx1 = sa[mt][0][2];
            #pragma unroll
            for (int nf = 0; nf < 8; ++nf) {
                mx0 = fmaxf(mx0, fmaxf(sa[mt][nf][0], sa[mt][nf][1]));
                mx1 = fmaxf(mx1, fmaxf(sa[mt][nf][2], sa[mt][nf][3]));
            }
            mx0 = fmaxf(mx0, __shfl_xor_sync(0xffffffffu, mx0, 1));
            mx0 = fmaxf(mx0, __shfl_xor_sync(0xffffffffu, mx0, 2));
            mx1 = fmaxf(mx1, __shfl_xor_sync(0xffffffffu, mx1, 1));
            mx1 = fmaxf(mx1, __shfl_xor_sync(0xffffffffu, mx1, 2));

            const float mn0 = fmaxf(m_[mt][0], mx0);
            const float mn1 = fmaxf(m_[mt][1], mx1);
            const float al0 = fast_exp(m_[mt][0] - mn0);
            const float al1 = fast_exp(m_[mt][1] - mn1);
            m_[mt][0] = mn0; m_[mt][1] = mn1;

            float rs0 = 0.0f, rs1 = 0.0f;
            #pragma unroll
            for (int nf = 0; nf < 8; ++nf) {
                sa[mt][nf][0] = fast_exp(sa[mt][nf][0] - mn0);
                sa[mt][nf][1] = fast_exp(sa[mt][nf][1] - mn0);
                sa[mt][nf][2] = fast_exp(sa[mt][nf][2] - mn1);
                sa[mt][nf][3] = fast_exp(sa[mt][nf][3] - mn1);
                rs0 += sa[mt][nf][0] + sa[mt][nf][1];
                rs1 += sa[mt][nf][2] + sa[mt][nf][3];
            }
            rs0 += __shfl_xor_sync(0xffffffffu, rs0, 1);
            rs0 += __shfl_xor_sync(0xffffffffu, rs0, 2);
            rs1 += __shfl_xor_sync(0xffffffffu, rs1, 1);
            rs1 += __shfl_xor_sync(0xffffffffu, rs1, 2);
            l_[mt][0] = l_[mt][0] * al0 + rs0;
            l_[mt][1] = l_[mt][1] * al1 + rs1;

            #pragma unroll
            for (int nf = 0; nf < 8; ++nf) {
                oa[mt][nf][0] *= al0; oa[mt][nf][1] *= al0;
                oa[mt][nf][2] *= al1; oa[mt][nf][3] *= al1;
            }
        }

        // ---- O += Phi*Vh + Plo*Vh + Phi*Vl; V frags shared by both mt ----
        #pragma unroll
        for (int ks = 0; ks < 4; ++ks) {
            uint32_t ah[2][4], al[2][4];
            #pragma unroll
            for (int mt = 0; mt < 2; ++mt) {
                const int f0 = 2 * ks, f1 = 2 * ks + 1;
                const float p00 = sa[mt][f0][0], p01 = sa[mt][f0][1];
                const float p02 = sa[mt][f0][2], p03 = sa[mt][f0][3];
                const float p10 = sa[mt][f1][0], p11 = sa[mt][f1][1];
                const float p12 = sa[mt][f1][2], p13 = sa[mt][f1][3];
                ah[mt][0] = pk2(p00, p01);
                ah[mt][1] = pk2(p02, p03);
                ah[mt][2] = pk2(p10, p11);
                ah[mt][3] = pk2(p12, p13);
                al[mt][0] = pk2(p00 - tobf(p00), p01 - tobf(p01));
                al[mt][1] = pk2(p02 - tobf(p02), p03 - tobf(p03));
                al[mt][2] = pk2(p10 - tobf(p10), p11 - tobf(p11));
                al[mt][3] = pk2(p12 - tobf(p12), p13 - tobf(p13));
            }
            #pragma unroll
            for (int nb = 0; nb < 4; ++nb) {
                uint32_t bh_[4], bl_[4];
                ldsm4(bh_, bVh_base + nb * (16 * FV_PITCH) + ks * 32);
                #pragma unroll
                for (int mt = 0; mt < 2; ++mt) {
                    hmma(oa[mt][nb * 2],     ah[mt], &bh_[0]);
                    hmma(oa[mt][nb * 2 + 1], ah[mt], &bh_[2]);
                    hmma(oa[mt][nb * 2],     al[mt], &bh_[0]);
                    hmma(oa[mt][nb * 2 + 1], al[mt], &bh_[2]);
                }
                ldsm4(bl_, bVl_base + nb * (16 * FV_PITCH) + ks * 32);
                #pragma unroll
                for (int mt = 0; mt < 2; ++mt) {
                    hmma(oa[mt][nb * 2],     ah[mt], &bl_[0]);
                    hmma(oa[mt][nb * 2 + 1], ah[mt], &bl_[2]);
                }
            }
        }
    }

    // ---- writeout ----
    const int b = bh >> 4;
    const int h = bh & 15;
    #pragma unroll
    for (int mt = 0; mt < 2; ++mt) {
        const int r0 = q0 + wid * 32 + mt * 16 + (lane >> 2);
        const float i0 = 1.0f / l_[mt][0];
        const float i1 = 1.0f / l_[mt][1];
        #pragma unroll
        for (int idx = 0; idx < 8; ++idx) {
            const int d = idx * 8 + (lane & 3) * 2;
            float* p0 = g_o + (size_t)(b * NSEQ + r0) * CDIM + h * DH + d;
            float* p1 = g_o + (size_t)(b * NSEQ + r0 + 8) * CDIM + h * DH + d;
            *(float2*)p0 = make_float2(oa[mt][idx][0] * i0, oa[mt][idx][1] * i0);
            *(float2*)p1 = make_float2(oa[mt][idx][2] * i1, oa[mt][idx][3] * i1);
        }
    }
}

// ---------------------------------------------------------------------------
// Launch
// ---------------------------------------------------------------------------
extern "C" void kernel_launch(void* const* d_in, const int* in_sizes, int n_in,
                              void* d_out, int out_size)
{
    const float* x      = (const float*)d_in[0];
    const float* cosp   = (const float*)d_in[1];
    const float* sinp   = (const float*)d_in[2];
    const float* w_qkv  = (const float*)d_in[3];
    const float* w_proj = (const float*)d_in[4];
    const float* qg     = (const float*)d_in[5];
    const float* kg     = (const float*)d_in[6];
    float* out          = (float*)d_out;
    (void)in_sizes; (void)n_in; (void)out_size;

    cudaFuncSetAttribute(gemm_mma<0>, cudaFuncAttributeMaxDynamicSharedMemorySize, GSMEM);
    cudaFuncSetAttribute(gemm_mma<1>, cudaFuncAttributeMaxDynamicSharedMemorySize, GSMEM);
    cudaFuncSetAttribute(flash_mma_kernel, cudaFuncAttributeMaxDynamicSharedMemorySize, FLASH2_SMEM);

    void *p_go, *p_xp, *p_op, *p_wqp, *p_wpp;
    cudaGetSymbolAddress(&p_go,  g_o);
    cudaGetSymbolAddress(&p_xp,  g_xp);
    cudaGetSymbolAddress(&p_op,  g_op);
    cudaGetSymbolAddress(&p_wqp, g_wqp);
    cudaGetSymbolAddress(&p_wpp, g_wpp);

    // 0) Pack dense-GEMM operands (vectorized: 4 elems/thread)
    pack_a_kernel<<<(MROWS*GK/4  + 255)/256, 256>>>(x,      (__nv_bfloat16*)p_xp,  MROWS*GK/4);
    pack_b_kernel<<<(3*CDIM*GK/4 + 255)/256, 256>>>(w_qkv,  (__nv_bfloat16*)p_wqp, 3*CDIM*GK/4);
    pack_b_kernel<<<(CDIM*GK/4   + 255)/256, 256>>>(w_proj, (__nv_bfloat16*)p_wpp, CDIM*GK/4);

    // 1) QKV GEMM -> fp32 g_q/g_k/g_v (B,H,N,D)
    gemm_mma<1><<<dim3(3*CDIM/128, MROWS/128), 128, GSMEM>>>(
        (const __nv_bfloat16*)p_xp, (const __nv_bfloat16*)p_wqp, nullptr, 3*CDIM);

    // 2) RMSNorm + RoPE + pack;  V transpose + split
    rmsrope_pack_kernel<<<dim3((2*BATCH*HEADS*NSEQ)/16, 2), 256>>>(cosp, sinp, qg, kg);
    vtrans_kernel<<<dim3(NSEQ/64, BATCH*HEADS), 128>>>();

    // 3) Flash attention (HMMA v3, 256-q blocks, 32 q-rows/warp) -> g_o (B,N,C)
    flash_mma_kernel<<<dim3(NSEQ/256, BATCH*HEADS), 256, FLASH2_SMEM>>>();

    // 4) Pack attention output, projection GEMM
    pack_a_kernel<<<(MROWS*GK/4 + 255)/256, 256>>>((const float*)p_go, (__nv_bfloat16*)p_op, MROWS*GK/4);
    gemm_mma<0><<<dim3(CDIM/128, MROWS/128), 128, GSMEM>>>(
        (const __nv_bfloat16*)p_op, (const __nv_bfloat16*)p_wpp, out, CDIM);
}

// round 16
// speedup vs baseline: 1.1920x; 1.0437x over previous
#include <cuda_runtime.h>
#include <cuda_bf16.h>
#include <math_constants.h>
#include <cstdint>

// Problem constants
#define BATCH 4
#define NSEQ  2048
#define CDIM  1024
#define HEADS 16
#define DH    64
#define MROWS (BATCH*NSEQ)                 // 8192
#define GK    1024
#define KP    3072                         // packed K (3-term split)
#define KQ    192                          // packed head dim (3-term split)
#define QKV_ELEMS (BATCH*HEADS*NSEQ*DH)
#define NROWS (BATCH*HEADS*NSEQ)           // 131072 attention rows
#define KSPLIT 2

// Scratch
__device__ float g_q[QKV_ELEMS];
__device__ float g_k[QKV_ELEMS];
__device__ float g_v[QKV_ELEMS];

__device__ __nv_bfloat16 g_xp [MROWS*KP];
__device__ __nv_bfloat16 g_op [MROWS*KP];
__device__ __nv_bfloat16 g_wqp[3*CDIM*KP];
__device__ __nv_bfloat16 g_wpp[CDIM*KP];

__device__ __nv_bfloat16 g_qp  [BATCH*HEADS*NSEQ*KQ];
__device__ __nv_bfloat16 g_kp  [BATCH*HEADS*NSEQ*KQ];
__device__ __nv_bfloat16 g_vthi[BATCH*HEADS*DH*NSEQ];
__device__ __nv_bfloat16 g_vtlo[BATCH*HEADS*DH*NSEQ];

// Split-K flash partials
__device__ float g_po[KSPLIT*NROWS*DH];    // unnormalized O per part
__device__ float g_pm[KSPLIT*NROWS];       // running max (log2 domain)
__device__ float g_pl[KSPLIT*NROWS];       // running denom

// ---------------------------------------------------------------------------
// helpers
// ---------------------------------------------------------------------------
__device__ __forceinline__ uint32_t smem_u32(const void* p) {
    uint32_t a;
    asm("{ .reg .u64 t; cvta.to.shared.u64 t, %1; cvt.u32.u64 %0, t; }" : "=r"(a) : "l"(p));
    return a;
}
__device__ __forceinline__ void ldsm4(uint32_t* r, uint32_t addr) {
    asm volatile("ldmatrix.sync.aligned.m8n8.x4.shared.b16 {%0,%1,%2,%3}, [%4];"
                 : "=r"(r[0]), "=r"(r[1]), "=r"(r[2]), "=r"(r[3]) : "r"(addr));
}
__device__ __forceinline__ void hmma(float* d, const uint32_t* a, const uint32_t* b) {
    asm volatile(
        "mma.sync.aligned.m16n8k16.row.col.f32.bf16.bf16.f32 "
        "{%0,%1,%2,%3}, {%4,%5,%6,%7}, {%8,%9}, {%0,%1,%2,%3};"
        : "+f"(d[0]), "+f"(d[1]), "+f"(d[2]), "+f"(d[3])
        : "r"(a[0]), "r"(a[1]), "r"(a[2]), "r"(a[3]), "r"(b[0]), "r"(b[1]));
}
__device__ __forceinline__ uint32_t pk2(float e0, float e1) {
    uint32_t r;
    asm("cvt.rn.bf16x2.f32 %0, %1, %2;" : "=r"(r) : "f"(e1), "f"(e0));
    return r;
}
__device__ __forceinline__ float tobf(float v) {
    return __bfloat162float(__float2bfloat16(v));
}
__device__ __forceinline__ void cpasync16(uint32_t dst, const void* src) {
    asm volatile("cp.async.cg.shared.global [%0], [%1], 16;" :: "r"(dst), "l"(src));
}
#define CP_COMMIT()  asm volatile("cp.async.commit_group;" ::: "memory")
#define CP_WAIT0()   asm volatile("cp.async.wait_group 0;" ::: "memory")

// FFMA-only 2^x (no MUFU), x <= 0, rel err ~2.4e-6.
__device__ __forceinline__ float fast_exp2(float x) {
    float y = fmaxf(x, -45.0f);
    const float C = 12582912.0f;                 // 1.5 * 2^23
    float z  = y + C;
    int   iz = __float_as_int(z);
    float f  = y - (z - C);
    float p  = 1.3333558e-3f;                    // ln2^5/120
    p = fmaf(p, f, 9.6181291e-3f);               // ln2^4/24
    p = fmaf(p, f, 5.5504109e-2f);               // ln2^3/6
    p = fmaf(p, f, 2.4022651e-1f);               // ln2^2/2
    p = fmaf(p, f, 6.9314718e-1f);               // ln2
    p = fmaf(p, f, 1.0f);
    int e = ((iz & 0x7FFFFF) - 0x400000) << 23;
    return __int_as_float(__float_as_int(p) + e);
}

// ---------------------------------------------------------------------------
// Pack kernels (vectorized): A=[hi|lo|hi], B=[hi|hi|lo], K'=3072.
// ---------------------------------------------------------------------------
__global__ __launch_bounds__(256)
void pack_a_kernel(const float* __restrict__ src, __nv_bfloat16* __restrict__ dst, int nquads)
{
    const int i = blockIdx.x * blockDim.x + threadIdx.x;
    if (i >= nquads) return;
    const int i4 = i * 4;
    const int m = i4 >> 10, k = i4 & 1023;
    const float4 v = *(const float4*)(src + i4);
    const uint32_t h01 = pk2(v.x, v.y), h23 = pk2(v.z, v.w);
    const uint32_t l01 = pk2(v.x - tobf(v.x), v.y - tobf(v.y));
    const uint32_t l23 = pk2(v.z - tobf(v.z), v.w - tobf(v.w));
    __nv_bfloat16* row = dst + (size_t)m * KP;
    *(uint2*)(row + k)        = make_uint2(h01, h23);
    *(uint2*)(row + k + 1024) = make_uint2(l01, l23);
    *(uint2*)(row + k + 2048) = make_uint2(h01, h23);
}
__global__ __launch_bounds__(256)
void pack_b_kernel(const float* __restrict__ src, __nv_bfloat16* __restrict__ dst, int nquads)
{
    const int i = blockIdx.x * blockDim.x + threadIdx.x;
    if (i >= nquads) return;
    const int i4 = i * 4;
    const int m = i4 >> 10, k = i4 & 1023;
    const float4 v = *(const float4*)(src + i4);
    const uint32_t h01 = pk2(v.x, v.y), h23 = pk2(v.z, v.w);
    const uint32_t l01 = pk2(v.x - tobf(v.x), v.y - tobf(v.y));
    const uint32_t l23 = pk2(v.z - tobf(v.z), v.w - tobf(v.w));
    __nv_bfloat16* row = dst + (size_t)m * KP;
    *(uint2*)(row + k)        = make_uint2(h01, h23);
    *(uint2*)(row + k + 1024) = make_uint2(h01, h23);
    *(uint2*)(row + k + 2048) = make_uint2(l01, l23);
}

// ---------------------------------------------------------------------------
// Dense NT GEMM v4 (measured best): 128x128 tile, 128 threads, warp 64x64,
// BK=64, 2-stage cp.async pipeline, 3 CTAs/SM. Row pitch 144B.
// ---------------------------------------------------------------------------
#define GPITCH_B 144
#define GTILE_B (128*GPITCH_B)
#define GSTAGE_B (2*GTILE_B)
#define GSMEM (2*GSTAGE_B)              // 73728 B

template<int EPI>
__global__ __launch_bounds__(128, 3)
void gemm_mma(const __nv_bfloat16* __restrict__ Ap, const __nv_bfloat16* __restrict__ Bp,
              float* __restrict__ C, int Nglob)
{
    extern __shared__ char smem[];
    const uint32_t sbase = smem_u32(smem);

    const int tid  = threadIdx.x;
    const int wid  = tid >> 5;
    const int lane = tid & 31;
    const int wm   = wid & 1;
    const int wn   = wid >> 1;
    const int m0   = blockIdx.y * 128;
    const int n0   = blockIdx.x * 128;

    const int lrow = tid >> 3;
    const int lq   = tid & 7;

    const uint32_t a_off = (uint32_t)((wm*64 + (lane & 15)) * GPITCH_B + (lane >> 4) * 16);
    const uint32_t b_off = (uint32_t)((wn*64 + (lane & 7) + ((lane >> 4) << 3)) * GPITCH_B
                                      + ((lane >> 3) & 1) * 16);

    float acc[4][8][4];
    #pragma unroll
    for (int mi = 0; mi < 4; ++mi)
        #pragma unroll
        for (int nf = 0; nf < 8; ++nf)
            #pragma unroll
            for (int j = 0; j < 4; ++j) acc[mi][nf][j] = 0.0f;

    const int T = KP / 64;

    auto issue = [&](int t) {
        const uint32_t sA = sbase + (t & 1) * GSTAGE_B;
        const uint32_t sB = sA + GTILE_B;
        const int kc = t * 64;
        #pragma unroll
        for (int i = 0; i < 8; ++i) {
            const int row = lrow + i * 16;
            cpasync16(sA + row * GPITCH_B + lq * 16,
                      Ap + (size_t)(m0 + row) * KP + kc + lq * 8);
        }
        #pragma unroll
        for (int i = 0; i < 8; ++i) {
            const int row = lrow + i * 16;
            cpasync16(sB + row * GPITCH_B + lq * 16,
                      Bp + (size_t)(n0 + row) * KP + kc + lq * 8);
        }
    };

    issue(0); CP_COMMIT();

    #pragma unroll 1
    for (int t = 0; t < T; ++t) {
        CP_WAIT0();
        __syncthreads();
        if (t + 1 < T) { issue(t + 1); CP_COMMIT(); }

        const uint32_t sA = sbase + (t & 1) * GSTAGE_B;
        const uint32_t sB = sA + GTILE_B;
        #pragma unroll
        for (int ks = 0; ks < 4; ++ks) {
            uint32_t a[4][4], b[4][4];
            #pragma unroll
            for (int mi = 0; mi < 4; ++mi)
                ldsm4(a[mi], sA + a_off + mi * (16*GPITCH_B) + ks * 32);
            #pragma unroll
            for (int nb = 0; nb < 4; ++nb)
                ldsm4(b[nb], sB + b_off + nb * (16*GPITCH_B) + ks * 32);
            #pragma unroll
            for (int mi = 0; mi < 4; ++mi)
                #pragma unroll
                for (int nb = 0; nb < 4; ++nb) {
                    hmma(acc[mi][nb*2],   a[mi], &b[nb][0]);
                    hmma(acc[mi][nb*2+1], a[mi], &b[nb][2]);
                }
        }
        __syncthreads();
    }

    const int rbase = m0 + wm * 64 + (lane >> 2);
    const int cbase = n0 + wn * 64 + (lane & 3) * 2;
    #pragma unroll
    for (int mi = 0; mi < 4; ++mi) {
        #pragma unroll
        for (int nf = 0; nf < 8; ++nf) {
            const int r0 = rbase + mi * 16;
            const int c  = cbase + nf * 8;
            const float2 v01 = make_float2(acc[mi][nf][0], acc[mi][nf][1]);
            const float2 v23 = make_float2(acc[mi][nf][2], acc[mi][nf][3]);
            if (EPI == 0) {
                *(float2*)(C + (size_t)r0 * Nglob + c)       = v01;
                *(float2*)(C + (size_t)(r0 + 8) * Nglob + c) = v23;
            } else {
                const int sel = c >> 10;
                const int rem = c & 1023;
                const int h   = rem >> 6;
                const int dcl = rem & 63;
                float* base = (sel == 0) ? g_q : ((sel == 1) ? g_k : g_v);
                {
                    const int m = r0, b = m >> 11, n = m & 2047;
                    *(float2*)(base + (size_t)((b * HEADS + h) * NSEQ + n) * DH + dcl) = v01;
                }
                {
                    const int m = r0 + 8, b = m >> 11, n = m & 2047;
                    *(float2*)(base + (size_t)((b * HEADS + h) * NSEQ + n) * DH + dcl) = v23;
                }
            }
        }
    }
}

// ---------------------------------------------------------------------------
// Fused RMSNorm + RoPE + split-bf16 pack.
// Q scale = 0.125 * log2(e) (score scale folded with base-2 softmax domain).
// ---------------------------------------------------------------------------
__global__ __launch_bounds__(256)
void rmsrope_pack_kernel(const float* __restrict__ cosp, const float* __restrict__ sinp,
                         const float* __restrict__ qg, const float* __restrict__ kg)
{
    const int wrow = (blockIdx.x * blockDim.x + threadIdx.x) >> 5;
    const int lane = threadIdx.x & 31;
    const int isq  = (blockIdx.y == 0);
    const float* arr   = isq ? g_q : g_k;
    const float* gamma = isq ? qg  : kg;

    const float* row = arr + (size_t)wrow * DH;
    const int n = wrow & (NSEQ - 1);

    float2 x = *(const float2*)(row + lane * 2);
    float ss = x.x * x.x + x.y * x.y;
    #pragma unroll
    for (int o = 16; o; o >>= 1) ss += __shfl_xor_sync(0xffffffffu, ss, o);
    const float norm = rsqrtf(ss * (1.0f / 64.0f) + 1e-6f);

    const float g0 = gamma[lane * 2], g1 = gamma[lane * 2 + 1];
    const float q0 = x.x * norm * g0;
    const float q1 = x.y * norm * g1;

    const float* cr = cosp + n * DH + lane * 2;
    const float* sr = sinp + n * DH + lane * 2;
    const float scale = isq ? 0.18033688011112042f : 1.0f;   // 0.125*log2(e) for q
    const float v0 = (q0 * cr[0] - q1 * sr[0]) * scale;
    const float v1 = (q1 * cr[1] + q0 * sr[1]) * scale;

    const uint32_t HP = pk2(v0, v1);
    const uint32_t LP = pk2(v0 - tobf(v0), v1 - tobf(v1));

    uint32_t* dst = (uint32_t*)((isq ? g_qp : g_kp) + (size_t)wrow * KQ);
    if (isq) { dst[lane] = HP; dst[32 + lane] = LP; dst[64 + lane] = HP; }
    else     { dst[lane] = HP; dst[32 + lane] = HP; dst[64 + lane] = LP; }
}

// ---------------------------------------------------------------------------
// V transpose + split: fp32 g_v (bh,n,d) -> bf16 g_vthi/g_vtlo (bh,d,n).
// ---------------------------------------------------------------------------
__global__ __launch_bounds__(128)
void vtrans_kernel()
{
    __shared__ float s[64 * 68];
    const int tid = threadIdx.x;
    const int n0  = blockIdx.x * 64;
    const int bh  = blockIdx.y;
    const float* src = g_v + ((size_t)bh * NSEQ + n0) * DH;

    #pragma unroll
    for (int it = 0; it < 8; ++it) {
        const int idx = tid + it * 128;
        const int n = idx >> 4, q = (idx & 15) * 4;
        *(float4*)&s[n * 68 + q] = *(const float4*)(src + (size_t)n * DH + q);
    }
    __syncthreads();

    const int d  = tid >> 1;
    const int nh = (tid & 1) * 32;
    uint32_t hibuf[16], lobuf[16];
    #pragma unroll
    for (int j = 0; j < 16; ++j) {
        const float a = s[(nh + 2*j) * 68 + d];
        const float b = s[(nh + 2*j + 1) * 68 + d];
        hibuf[j] = pk2(a, b);
        lobuf[j] = pk2(a - tobf(a), b - tobf(b));
    }
    uint32_t* dh = (uint32_t*)(g_vthi + ((size_t)bh * DH + d) * NSEQ + n0 + nh);
    uint32_t* dl = (uint32_t*)(g_vtlo + ((size_t)bh * DH + d) * NSEQ + n0 + nh);
    #pragma unroll
    for (int j = 0; j < 16; ++j) { dh[j] = hibuf[j]; dl[j] = lobuf[j]; }
}

// ---------------------------------------------------------------------------
// Flash attention v5 = measured-best v3 loop + split-K(2).
// Block: (256 q-rows, bh, part); part handles keys [part*1024, part*1024+1024).
// Writes unnormalized O + per-row (m, l) partials (base-2 softmax domain).
// smem unchanged: Q 102400, K 2x25600, V 2x18432 = 190464 B.
// ---------------------------------------------------------------------------
#define FQ_PITCH 400
#define FV_PITCH 144
#define F_SQ   0
#define F_SK   102400                     // + st*25600
#define F_SV   153600                     // + st*18432 ; lo at +9216
#define FLASH2_SMEM 190464

__global__ __launch_bounds__(256)
void flash_mma_kernel()
{
    extern __shared__ char sm[];
    const uint32_t sb = smem_u32(sm);
    const int tid  = threadIdx.x;
    const int wid  = tid >> 5;
    const int lane = tid & 31;
    const int q0   = blockIdx.x * 256;
    const int bh   = blockIdx.y;
    const int part = blockIdx.z;
    const int kt0  = part * (NSEQ / 64 / KSPLIT);        // 16 iters per part

    const __nv_bfloat16* Qg  = g_qp   + ((size_t)bh * NSEQ + q0) * KQ;
    const __nv_bfloat16* Kg  = g_kp   + (size_t)bh * NSEQ * KQ;
    const __nv_bfloat16* Vhg = g_vthi + (size_t)bh * DH * NSEQ;
    const __nv_bfloat16* Vlg = g_vtlo + (size_t)bh * DH * NSEQ;

    auto issue_kv = [&](int kt, int st) {
        const uint32_t sk = sb + F_SK + st * 25600;
        const uint32_t sv = sb + F_SV + st * 18432;
        #pragma unroll
        for (int i = 0; i < 6; ++i) {
            const int idx = tid + i * 256;
            const int row = idx / 24, q = idx % 24;
            cpasync16(sk + row * FQ_PITCH + q * 16,
                      Kg + (size_t)(kt * 64 + row) * KQ + q * 8);
        }
        #pragma unroll
        for (int i = 0; i < 2; ++i) {
            const int idx = tid + i * 256;
            const int d = idx >> 3, q = idx & 7;
            cpasync16(sv + d * FV_PITCH + q * 16,
                      Vhg + (size_t)d * NSEQ + kt * 64 + q * 8);
        }
        #pragma unroll
        for (int i = 0; i < 2; ++i) {
            const int idx = tid + i * 256;
            const int d = idx >> 3, q = idx & 7;
            cpasync16(sv + 9216 + d * FV_PITCH + q * 16,
                      Vlg + (size_t)d * NSEQ + kt * 64 + q * 8);
        }
    };

    issue_kv(kt0, 0); CP_COMMIT();

    // Load Q tile: 256 rows x 24 quads, 24 per thread
    #pragma unroll
    for (int i = 0; i < 24; ++i) {
        const int idx = tid + i * 256;
        const int row = idx / 24, q = idx % 24;
        *(uint4*)(sm + F_SQ + row * FQ_PITCH + q * 16) =
            *(const uint4*)(Qg + (size_t)row * KQ + q * 8);
    }

    uint32_t a_base[2];
    #pragma unroll
    for (int mt = 0; mt < 2; ++mt)
        a_base[mt] = sb + F_SQ + (wid * 32 + mt * 16 + (lane & 15)) * FQ_PITCH
                     + (lane >> 4) * 16;
    const uint32_t bK_off = ((lane & 7) + ((lane >> 4) << 3)) * FQ_PITCH + ((lane >> 3) & 1) * 16;
    const uint32_t bV_off = ((lane & 7) + ((lane >> 4) << 3)) * FV_PITCH + ((lane >> 3) & 1) * 16;

    float m_[2][2], l_[2][2];
    float oa[2][8][4];
    #pragma unroll
    for (int mt = 0; mt < 2; ++mt) {
        m_[mt][0] = -CUDART_INF_F; m_[mt][1] = -CUDART_INF_F;
        l_[mt][0] = 0.0f; l_[mt][1] = 0.0f;
        #pragma unroll
        for (int i = 0; i < 8; ++i)
            #pragma unroll
            for (int j = 0; j < 4; ++j) oa[mt][i][j] = 0.0f;
    }

    const int ktend = kt0 + NSEQ / 64 / KSPLIT;
    #pragma unroll 1
    for (int kt = kt0; kt < ktend; ++kt) {
        const int st = kt & 1;
        CP_WAIT0();
        __syncthreads();
        if (kt + 1 < ktend) { issue_kv(kt + 1, st ^ 1); CP_COMMIT(); }

        const uint32_t bK_base  = sb + F_SK + st * 25600 + bK_off;
        const uint32_t bVh_base = sb + F_SV + st * 18432 + bV_off;
        const uint32_t bVl_base = bVh_base + 9216;

        // ---- S = Q * K^T over k' = 192 (12 k-steps); K frags shared by both mt ----
        float sa[2][8][4];
        #pragma unroll
        for (int mt = 0; mt < 2; ++mt)
            #pragma unroll
            for (int i = 0; i < 8; ++i)
                #pragma unroll
                for (int j = 0; j < 4; ++j) sa[mt][i][j] = 0.0f;

        #pragma unroll
        for (int ks = 0; ks < 12; ++ks) {
            uint32_t b[4][4];
            #pragma unroll
            for (int nb = 0; nb < 4; ++nb)
                ldsm4(b[nb], bK_base + nb * (16 * FQ_PITCH) + ks * 32);
            #pragma unroll
            for (int mt = 0; mt < 2; ++mt) {
                uint32_t a[4];
                ldsm4(a, a_base[mt] + ks * 32);
                #pragma unroll
                for (int nb = 0; nb < 4; ++nb) {
                    hmma(sa[mt][nb * 2],     a, &b[nb][0]);
                    hmma(sa[mt][nb * 2 + 1], a, &b[nb][2]);
                }
            }
        }

        // ---- online softmax per mt (base-2 domain) ----
        #pragma unroll
        for (int mt = 0; mt < 2; ++mt) {
            float mx0 = sa[mt][0][0], mx1 = sa[mt][0][2];
            #pragma unroll
            for (int nf = 0; nf < 8; ++nf) {
                mx0 = fmaxf(mx0, fmaxf(sa[mt][nf][0], sa[mt][nf][1]));
                mx1 = fmaxf(mx1, fmaxf(sa[mt][nf][2], sa[mt][nf][3]));
            }
            mx0 = fmaxf(mx0, __shfl_xor_sync(0xffffffffu, mx0, 1));
            mx0 = fmaxf(mx0, __shfl_xor_sync(0xffffffffu, mx0, 2));
            mx1 = fmaxf(mx1, __shfl_xor_sync(0xffffffffu, mx1, 1));
            mx1 = fmaxf(mx1, __shfl_xor_sync(0xffffffffu, mx1, 2));

            const float mn0 = fmaxf(m_[mt][0], mx0);
            const float mn1 = fmaxf(m_[mt][1], mx1);
            const float al0 = fast_exp2(m_[mt][0] - mn0);
            const float al1 = fast_exp2(m_[mt][1] - mn1);
            m_[mt][0] = mn0; m_[mt][1] = mn1;

            float rs0 = 0.0f, rs1 = 0.0f;
            #pragma unroll
            for (int nf = 0; nf < 8; ++nf) {
                sa[mt][nf][0] = fast_exp2(sa[mt][nf][0] - mn0);
                sa[mt][nf][1] = fast_exp2(sa[mt][nf][1] - mn0);
                sa[mt][nf][2] = fast_exp2(sa[mt][nf][2] - mn1);
                sa[mt][nf][3] = fast_exp2(sa[mt][nf][3] - mn1);
                rs0 += sa[mt][nf][0] + sa[mt][nf][1];
                rs1 += sa[mt][nf][2] + sa[mt][nf][3];
            }
            rs0 += __shfl_xor_sync(0xffffffffu, rs0, 1);
            rs0 += __shfl_xor_sync(0xffffffffu, rs0, 2);
            rs1 += __shfl_xor_sync(0xffffffffu, rs1, 1);
            rs1 += __shfl_xor_sync(0xffffffffu, rs1, 2);
            l_[mt][0] = l_[mt][0] * al0 + rs0;
            l_[mt][1] = l_[mt][1] * al1 + rs1;

            #pragma unroll
            for (int nf = 0; nf < 8; ++nf) {
                oa[mt][nf][0] *= al0; oa[mt][nf][1] *= al0;
                oa[mt][nf][2] *= al1; oa[mt][nf][3] *= al1;
            }
        }

        // ---- O += Phi*Vh + Plo*Vh + Phi*Vl; V frags shared by both mt ----
        #pragma unroll
        for (int ks = 0; ks < 4; ++ks) {
            uint32_t ah[2][4], al[2][4];
            #pragma unroll
            for (int mt = 0; mt < 2; ++mt) {
                const int f0 = 2 * ks, f1 = 2 * ks + 1;
                const float p00 = sa[mt][f0][0], p01 = sa[mt][f0][1];
                const float p02 = sa[mt][f0][2], p03 = sa[mt][f0][3];
                const float p10 = sa[mt][f1][0], p11 = sa[mt][f1][1];
                const float p12 = sa[mt][f1][2], p13 = sa[mt][f1][3];
                ah[mt][0] = pk2(p00, p01);
                ah[mt][1] = pk2(p02, p03);
                ah[mt][2] = pk2(p10, p11);
                ah[mt][3] = pk2(p12, p13);
                al[mt][0] = pk2(p00 - tobf(p00), p01 - tobf(p01));
                al[mt][1] = pk2(p02 - tobf(p02), p03 - tobf(p03));
                al[mt][2] = pk2(p10 - tobf(p10), p11 - tobf(p11));
                al[mt][3] = pk2(p12 - tobf(p12), p13 - tobf(p13));
            }
            #pragma unroll
            for (int nb = 0; nb < 4; ++nb) {
                uint32_t bh_[4], bl_[4];
                ldsm4(bh_, bVh_base + nb * (16 * FV_PITCH) + ks * 32);
                #pragma unroll
                for (int mt = 0; mt < 2; ++mt) {
                    hmma(oa[mt][nb * 2],     ah[mt], &bh_[0]);
                    hmma(oa[mt][nb * 2 + 1], ah[mt], &bh_[2]);
                    hmma(oa[mt][nb * 2],     al[mt], &bh_[0]);
                    hmma(oa[mt][nb * 2 + 1], al[mt], &bh_[2]);
                }
                ldsm4(bl_, bVl_base + nb * (16 * FV_PITCH) + ks * 32);
                #pragma unroll
                for (int mt = 0; mt < 2; ++mt) {
                    hmma(oa[mt][nb * 2],     ah[mt], &bl_[0]);
                    hmma(oa[mt][nb * 2 + 1], ah[mt], &bl_[2]);
                }
            }
        }
    }

    // ---- writeout: unnormalized partials + (m,l) ----
    float* po = g_po + ((size_t)part * NROWS + (size_t)bh * NSEQ) * DH;
    float* pm = g_pm + (size_t)part * NROWS + (size_t)bh * NSEQ;
    float* pl = g_pl + (size_t)part * NROWS + (size_t)bh * NSEQ;
    #pragma unroll
    for (int mt = 0; mt < 2; ++mt) {
        const int r0 = q0 + wid * 32 + mt * 16 + (lane >> 2);
        if ((lane & 3) == 0) {
            pm[r0]     = m_[mt][0];  pl[r0]     = l_[mt][0];
            pm[r0 + 8] = m_[mt][1];  pl[r0 + 8] = l_[mt][1];
        }
        #pragma unroll
        for (int idx = 0; idx < 8; ++idx) {
            const int d = idx * 8 + (lane & 3) * 2;
            *(float2*)(po + (size_t)r0 * DH + d)       = make_float2(oa[mt][idx][0], oa[mt][idx][1]);
            *(float2*)(po + (size_t)(r0 + 8) * DH + d) = make_float2(oa[mt][idx][2], oa[mt][idx][3]);
        }
    }
}

// ---------------------------------------------------------------------------
// Split-K combine + proj-A pack: merges 2 partials per row, writes packed
// [hi|lo|hi] rows of g_op directly. One warp per row (32 lanes x 2 d each).
// ---------------------------------------------------------------------------
__global__ __launch_bounds__(256)
void combine_kernel()
{
    const int tid  = threadIdx.x;
    const int lane = tid & 31;
    const int row  = blockIdx.x * 8 + (tid >> 5);      // bh*2048 + q
    const int bh = row >> 11, q = row & 2047;
    const int b = bh >> 4, h = bh & 15;

    const float m0 = g_pm[row], m1 = g_pm[NROWS + row];
    const float l0 = g_pl[row], l1 = g_pl[NROWS + row];
    const float mm = fmaxf(m0, m1);
    const float a0 = fast_exp2(m0 - mm);
    const float a1 = fast_exp2(m1 - mm);
    const float inv = 1.0f / (l0 * a0 + l1 * a1);

    const int d = lane * 2;
    const size_t base = (size_t)row * DH + d;
    const float2 o0 = *(const float2*)(g_po + base);
    const float2 o1 = *(const float2*)(g_po + (size_t)NROWS * DH + base);
    const float v0 = (o0.x * a0 + o1.x * a1) * inv;
    const float v1 = (o0.y * a0 + o1.y * a1) * inv;

    const uint32_t hp = pk2(v0, v1);
    const uint32_t lp = pk2(v0 - tobf(v0), v1 - tobf(v1));
    __nv_bfloat16* rp = g_op + (size_t)(b * NSEQ + q) * KP + h * DH + d;
    *(uint32_t*)rp           = hp;
    *(uint32_t*)(rp + 1024)  = lp;
    *(uint32_t*)(rp + 2048)  = hp;
}

// ---------------------------------------------------------------------------
// Launch
// ---------------------------------------------------------------------------
extern "C" void kernel_launch(void* const* d_in, const int* in_sizes, int n_in,
                              void* d_out, int out_size)
{
    const float* x      = (const float*)d_in[0];
    const float* cosp   = (const float*)d_in[1];
    const float* sinp   = (const float*)d_in[2];
    const float* w_qkv  = (const float*)d_in[3];
    const float* w_proj = (const float*)d_in[4];
    const float* qg     = (const float*)d_in[5];
    const float* kg     = (const float*)d_in[6];
    float* out          = (float*)d_out;
    (void)in_sizes; (void)n_in; (void)out_size;

    cudaFuncSetAttribute(gemm_mma<0>, cudaFuncAttributeMaxDynamicSharedMemorySize, GSMEM);
    cudaFuncSetAttribute(gemm_mma<1>, cudaFuncAttributeMaxDynamicSharedMemorySize, GSMEM);
    cudaFuncSetAttribute(flash_mma_kernel, cudaFuncAttributeMaxDynamicSharedMemorySize, FLASH2_SMEM);

    void *p_xp, *p_op, *p_wqp, *p_wpp;
    cudaGetSymbolAddress(&p_xp,  g_xp);
    cudaGetSymbolAddress(&p_op,  g_op);
    cudaGetSymbolAddress(&p_wqp, g_wqp);
    cudaGetSymbolAddress(&p_wpp, g_wpp);

    // 0) Pack dense-GEMM operands
    pack_a_kernel<<<(MROWS*GK/4  + 255)/256, 256>>>(x,      (__nv_bfloat16*)p_xp,  MROWS*GK/4);
    pack_b_kernel<<<(3*CDIM*GK/4 + 255)/256, 256>>>(w_qkv,  (__nv_bfloat16*)p_wqp, 3*CDIM*GK/4);
    pack_b_kernel<<<(CDIM*GK/4   + 255)/256, 256>>>(w_proj, (__nv_bfloat16*)p_wpp, CDIM*GK/4);

    // 1) QKV GEMM -> fp32 g_q/g_k/g_v (B,H,N,D)
    gemm_mma<1><<<dim3(3*CDIM/128, MROWS/128), 128, GSMEM>>>(
        (const __nv_bfloat16*)p_xp, (const __nv_bfloat16*)p_wqp, nullptr, 3*CDIM);

    // 2) RMSNorm + RoPE + pack (q scale incl. log2e);  V transpose + split
    rmsrope_pack_kernel<<<dim3((2*BATCH*HEADS*NSEQ)/16, 2), 256>>>(cosp, sinp, qg, kg);
    vtrans_kernel<<<dim3(NSEQ/64, BATCH*HEADS), 128>>>();

    // 3) Flash attention split-K(2) -> partials; combine -> packed g_op
    flash_mma_kernel<<<dim3(NSEQ/256, BATCH*HEADS, KSPLIT), 256, FLASH2_SMEM>>>();
    combine_kernel<<<NROWS/8, 256>>>();

    // 4) Projection GEMM (reads packed g_op directly)
    gemm_mma<0><<<dim3(CDIM/128, MROWS/128), 128, GSMEM>>>(
        (const __nv_bfloat16*)p_op, (const __nv_bfloat16*)p_wpp, out, CDIM);
}